// round 8
// baseline (speedup 1.0000x reference)
#include <cuda_runtime.h>
#include <cuda_bf16.h>
#include <cstdint>
#include <math.h>

#define DM 1024
#define TS 2048
#define BB 4
#define NH 16
#define HD 64
#define K3 (3*DM)            // split-bf16 expanded K = 3072
#define MROWS (BB*TS)        // 8192
#define NEG_BIG (-1e30f)

// ---------------------------------------------------------------------------
// Scratch (__device__ globals: allocation-free rule)
// ---------------------------------------------------------------------------
__device__ float g_qkv[(size_t)MROWS * 3 * DM];        // fp32 QKV for attention
__device__ float g_attn[(size_t)MROWS * DM];           // fp32 attention output
__device__ __nv_bfloat16 g_x3[(size_t)MROWS * K3];     // [M, 3K] split x
__device__ __nv_bfloat16 g_a3[(size_t)MROWS * K3];     // [M, 3K] split attn-out
__device__ __nv_bfloat16 g_wqkv3[(size_t)(3*DM) * K3]; // [N, 3K] split w_qkv^T
__device__ __nv_bfloat16 g_wout3[(size_t)DM * K3];     // [N, 3K] split w_out^T

// ---------------------------------------------------------------------------
__device__ __forceinline__ uint32_t smem_u32(const void* p) {
    uint32_t a;
    asm("{ .reg .u64 t; cvta.to.shared.u64 t, %1; cvt.u32.u64 %0, t; }"
        : "=r"(a) : "l"(p));
    return a;
}
#define CP_ASYNC16(sm, gm) \
    asm volatile("cp.async.cg.shared.global [%0], [%1], 16;" :: "r"(sm), "l"(gm))
#define CP_COMMIT() asm volatile("cp.async.commit_group;" ::: "memory")
#define CP_WAIT0()  asm volatile("cp.async.wait_group 0;" ::: "memory")
#define CP_WAIT1()  asm volatile("cp.async.wait_group 1;" ::: "memory")

#define LDSM_X4(r0,r1,r2,r3,addr) \
    asm volatile("ldmatrix.sync.aligned.m8n8.x4.shared.b16 {%0,%1,%2,%3}, [%4];" \
        : "=r"(r0),"=r"(r1),"=r"(r2),"=r"(r3) : "r"(addr))
#define MMA_BF16(d, a, b0, b1) \
    asm volatile("mma.sync.aligned.m16n8k16.row.col.f32.bf16.bf16.f32 " \
        "{%0,%1,%2,%3}, {%4,%5,%6,%7}, {%8,%9}, {%0,%1,%2,%3};" \
        : "+f"((d)[0]), "+f"((d)[1]), "+f"((d)[2]), "+f"((d)[3]) \
        : "r"((a)[0]), "r"((a)[1]), "r"((a)[2]), "r"((a)[3]), "r"(b0), "r"(b1))

// ---------------------------------------------------------------------------
// Split conversion kernels (bf16 hi/lo, K-concatenated)
// act: [hi | hi | lo]   weightT: [hi | lo | hi]  -> hi*hi + hi*lo + lo*hi
// ---------------------------------------------------------------------------
__global__ __launch_bounds__(256) void split_act_kernel(
    const float* __restrict__ in, __nv_bfloat16* __restrict__ out, int K)
{
    size_t idx = (size_t)blockIdx.x * 256 + threadIdx.x;
    int m = (int)(idx / K);
    int k = (int)(idx % K);
    float a = in[idx];
    __nv_bfloat16 hi = __float2bfloat16(a);
    __nv_bfloat16 lo = __float2bfloat16(a - __bfloat162float(hi));
    size_t base = (size_t)m * (3 * K);
    out[base + k]         = hi;
    out[base + K + k]     = hi;
    out[base + 2 * K + k] = lo;
}

__global__ void split_wt_kernel(const float* __restrict__ w,
                                __nv_bfloat16* __restrict__ out, int K, int N)
{
    __shared__ float t[32][33];
    int k0 = blockIdx.y * 32, n0 = blockIdx.x * 32;
    t[threadIdx.y][threadIdx.x] = w[(size_t)(k0 + threadIdx.y) * N + n0 + threadIdx.x];
    __syncthreads();
    float a = t[threadIdx.x][threadIdx.y];      // w[k0+tx][n0+ty]
    int n = n0 + threadIdx.y, k = k0 + threadIdx.x;
    __nv_bfloat16 hi = __float2bfloat16(a);
    __nv_bfloat16 lo = __float2bfloat16(a - __bfloat162float(hi));
    size_t base = (size_t)n * (3 * K);
    out[base + k]         = hi;
    out[base + K + k]     = lo;
    out[base + 2 * K + k] = hi;
}

// ---------------------------------------------------------------------------
// HMMA GEMM: C[M,N] = A[M,K3] @ Bt[N,K3]^T + bias (fp32 out)
// 128x128 CTA tile, BK=32, 8 warps (2x4), warp tile 64x32,
// mma.m16n8k16 bf16, ldmatrix (both operands NON-trans: A=[M,K], Bt=[N,K]
// are both k-contiguous, matching the .row.col fragment layouts),
// cp.async double buffering. Smem rows padded to 40 bf16 (80B stride).
// ---------------------------------------------------------------------------
#define BK 32
#define SSTR 40     // smem row stride in bf16
#define NC (K3 / BK)   // 96

__device__ __forceinline__ void stage_load(
    __nv_bfloat16* as, __nv_bfloat16* bs,
    const __nv_bfloat16* __restrict__ A, const __nv_bfloat16* __restrict__ Bt,
    int row0, int col0, int k0, int tid)
{
    #pragma unroll
    for (int j = 0; j < 2; j++) {
        int i = tid + j * 256;          // 0..511
        int r = i >> 2;                 // 0..127
        int u = i & 3;                  // 16B unit (8 bf16)
        uint32_t sa = smem_u32(as + r * SSTR + u * 8);
        CP_ASYNC16(sa, A + (size_t)(row0 + r) * K3 + k0 + u * 8);
        uint32_t sb = smem_u32(bs + r * SSTR + u * 8);
        CP_ASYNC16(sb, Bt + (size_t)(col0 + r) * K3 + k0 + u * 8);
    }
}

__global__ __launch_bounds__(256) void gemm_mma_kernel(
    const __nv_bfloat16* __restrict__ A, const __nv_bfloat16* __restrict__ Bt,
    const float* __restrict__ bias, float* __restrict__ C, int N)
{
    __shared__ __align__(16) __nv_bfloat16 As[2][128 * SSTR];
    __shared__ __align__(16) __nv_bfloat16 Bs[2][128 * SSTR];

    const int tid  = threadIdx.x;
    const int lane = tid & 31;
    const int warp = tid >> 5;
    const int wr = warp >> 2;           // 0..1
    const int wc = warp & 3;            // 0..3
    const int m0 = wr * 64;
    const int n0 = wc * 32;
    const int row0 = blockIdx.y * 128;
    const int col0 = blockIdx.x * 128;

    // ldmatrix lane addressing: row within 16, col-half select
    const int lrow  = (lane & 7) + 8 * ((lane >> 3) & 1);  // 0..15
    const int lcol8 = (lane >> 4) * 8;                     // 0 or 8

    float acc[4][4][4];
    #pragma unroll
    for (int mf = 0; mf < 4; mf++)
        #pragma unroll
        for (int nf = 0; nf < 4; nf++)
            #pragma unroll
            for (int e = 0; e < 4; e++) acc[mf][nf][e] = 0.f;

    stage_load(As[0], Bs[0], A, Bt, row0, col0, 0, tid);
    CP_COMMIT();

    for (int c = 0; c < NC; c++) {
        int buf = c & 1;
        if (c + 1 < NC) {
            stage_load(As[buf ^ 1], Bs[buf ^ 1], A, Bt, row0, col0, (c + 1) * BK, tid);
            CP_COMMIT();
            CP_WAIT1();
        } else {
            CP_WAIT0();
        }
        __syncthreads();

        const __nv_bfloat16* as = As[buf];
        const __nv_bfloat16* bs = Bs[buf];

        #pragma unroll
        for (int ks = 0; ks < 2; ks++) {
            int kb = ks * 16;
            uint32_t af[4][4];
            #pragma unroll
            for (int mf = 0; mf < 4; mf++) {
                uint32_t addr = smem_u32(as + (m0 + mf * 16 + lrow) * SSTR + kb + lcol8);
                LDSM_X4(af[mf][0], af[mf][1], af[mf][2], af[mf][3], addr);
            }
            uint32_t bfr[2][4];
            #pragma unroll
            for (int bp = 0; bp < 2; bp++) {
                // NON-trans: Bt rows are [n][k], exactly the B fragment layout
                uint32_t addr = smem_u32(bs + (n0 + bp * 16 + lrow) * SSTR + kb + lcol8);
                LDSM_X4(bfr[bp][0], bfr[bp][1], bfr[bp][2], bfr[bp][3], addr);
            }
            #pragma unroll
            for (int mf = 0; mf < 4; mf++) {
                #pragma unroll
                for (int nf = 0; nf < 4; nf++) {
                    int bp = nf >> 1, sel = nf & 1;
                    MMA_BF16(acc[mf][nf], af[mf], bfr[bp][sel], bfr[bp][sel + 2]);
                }
            }
        }
        __syncthreads();
    }

    // Epilogue: fp32 + bias, direct to gmem
    const int r0l = lane >> 2;          // 0..7
    const int c0l = (lane & 3) * 2;     // 0,2,4,6
    #pragma unroll
    for (int nf = 0; nf < 4; nf++) {
        int col = col0 + n0 + nf * 8 + c0l;
        float2 bv = *(const float2*)(bias + col);
        #pragma unroll
        for (int mf = 0; mf < 4; mf++) {
            int rowA = row0 + m0 + mf * 16 + r0l;
            float2 v0 = make_float2(acc[mf][nf][0] + bv.x, acc[mf][nf][1] + bv.y);
            float2 v1 = make_float2(acc[mf][nf][2] + bv.x, acc[mf][nf][3] + bv.y);
            *(float2*)(C + (size_t)rowA * N + col)       = v0;
            *(float2*)(C + (size_t)(rowA + 8) * N + col) = v1;
        }
    }
}

// ---------------------------------------------------------------------------
// Flash attention (causal, fp32) — unchanged (R9 target)
// ---------------------------------------------------------------------------
__device__ __forceinline__ float redmax16(float v) {
    v = fmaxf(v, __shfl_xor_sync(0xffffffffu, v, 1));
    v = fmaxf(v, __shfl_xor_sync(0xffffffffu, v, 2));
    v = fmaxf(v, __shfl_xor_sync(0xffffffffu, v, 4));
    v = fmaxf(v, __shfl_xor_sync(0xffffffffu, v, 8));
    return v;
}
__device__ __forceinline__ float redsum16(float v) {
    v += __shfl_xor_sync(0xffffffffu, v, 1);
    v += __shfl_xor_sync(0xffffffffu, v, 2);
    v += __shfl_xor_sync(0xffffffffu, v, 4);
    v += __shfl_xor_sync(0xffffffffu, v, 8);
    return v;
}

#define ATTN_SMEM_FLOATS (64*64 + 64*64 + 64*68 + 64*68)
#define ATTN_SMEM_BYTES  (ATTN_SMEM_FLOATS * 4)

__global__ __launch_bounds__(256) void attn_kernel(
    const float* __restrict__ qkv, float* __restrict__ out)
{
    extern __shared__ __align__(16) float sm[];
    float* Qs = sm;                      // [d][qi]  stride 64 (transposed)
    float* Ks = sm + 4096;               // [d][kj]  stride 64 (transposed)
    float* Vs = sm + 8192;               // [kj][d]  stride 68
    float* Ps = sm + 8192 + 64 * 68;     // [qi][kj] stride 68

    const int tid = threadIdx.x;
    const int tx  = tid & 15;
    const int ty  = tid >> 4;
    const int qt  = blockIdx.x;
    const int b   = blockIdx.y >> 4;
    const int h   = blockIdx.y & 15;

    const int lr = tid >> 2;
    const int lc = tid & 3;

    const float* qbase = qkv + ((size_t)b * TS + (size_t)qt * 64) * (3 * DM) + h * HD;

    #pragma unroll
    for (int cc = 0; cc < 4; cc++) {
        int c = (lc + cc * 4) * 4;
        float4 v = *(const float4*)(qbase + (size_t)lr * (3 * DM) + c);
        Qs[(c + 0) * 64 + lr] = v.x;
        Qs[(c + 1) * 64 + lr] = v.y;
        Qs[(c + 2) * 64 + lr] = v.z;
        Qs[(c + 3) * 64 + lr] = v.w;
    }

    float o[4][4];
    float m_i[4], l_i[4];
    #pragma unroll
    for (int i = 0; i < 4; i++) {
        m_i[i] = NEG_BIG; l_i[i] = 0.f;
        #pragma unroll
        for (int j = 0; j < 4; j++) o[i][j] = 0.f;
    }

    for (int kt = 0; kt <= qt; kt++) {
        __syncthreads();
        const float* kbase = qkv + ((size_t)b * TS + (size_t)kt * 64) * (3 * DM) + DM + h * HD;
        const float* vbase = kbase + DM;
        #pragma unroll
        for (int cc = 0; cc < 4; cc++) {
            int c = (lc + cc * 4) * 4;
            float4 kv = *(const float4*)(kbase + (size_t)lr * (3 * DM) + c);
            Ks[(c + 0) * 64 + lr] = kv.x;
            Ks[(c + 1) * 64 + lr] = kv.y;
            Ks[(c + 2) * 64 + lr] = kv.z;
            Ks[(c + 3) * 64 + lr] = kv.w;
            float4 vv = *(const float4*)(vbase + (size_t)lr * (3 * DM) + c);
            *(float4*)&Vs[lr * 68 + c] = vv;
        }
        __syncthreads();

        float s[4][4];
        #pragma unroll
        for (int i = 0; i < 4; i++)
            #pragma unroll
            for (int j = 0; j < 4; j++) s[i][j] = 0.f;

        #pragma unroll 16
        for (int kk = 0; kk < 64; kk++) {
            float4 q4 = *(const float4*)&Qs[kk * 64 + ty * 4];
            float4 k4 = *(const float4*)&Ks[kk * 64 + tx * 4];
            float qa[4] = {q4.x, q4.y, q4.z, q4.w};
            float ka[4] = {k4.x, k4.y, k4.z, k4.w};
            #pragma unroll
            for (int i = 0; i < 4; i++)
                #pragma unroll
                for (int j = 0; j < 4; j++)
                    s[i][j] = fmaf(qa[i], ka[j], s[i][j]);
        }

        const float sc = 0.125f;
        const bool diag = (kt == qt);
        #pragma unroll
        for (int i = 0; i < 4; i++) {
            #pragma unroll
            for (int j = 0; j < 4; j++) {
                float v = s[i][j] * sc;
                if (diag && (tx * 4 + j) > (ty * 4 + i)) v = NEG_BIG;
                s[i][j] = v;
            }
        }

        #pragma unroll
        for (int i = 0; i < 4; i++) {
            float mm = fmaxf(fmaxf(s[i][0], s[i][1]), fmaxf(s[i][2], s[i][3]));
            mm = redmax16(mm);
            float mnew  = fmaxf(m_i[i], mm);
            float alpha = __expf(m_i[i] - mnew);
            m_i[i] = mnew;
            float p0 = __expf(s[i][0] - mnew);
            float p1 = __expf(s[i][1] - mnew);
            float p2 = __expf(s[i][2] - mnew);
            float p3 = __expf(s[i][3] - mnew);
            float sum = redsum16(p0 + p1 + p2 + p3);
            l_i[i] = l_i[i] * alpha + sum;
            o[i][0] *= alpha; o[i][1] *= alpha; o[i][2] *= alpha; o[i][3] *= alpha;
            *(float4*)&Ps[(ty * 4 + i) * 68 + tx * 4] = make_float4(p0, p1, p2, p3);
        }
        __syncthreads();

        #pragma unroll
        for (int kk = 0; kk < 64; kk += 4) {
            float4 v0 = *(const float4*)&Vs[(kk + 0) * 68 + tx * 4];
            float4 v1 = *(const float4*)&Vs[(kk + 1) * 68 + tx * 4];
            float4 v2 = *(const float4*)&Vs[(kk + 2) * 68 + tx * 4];
            float4 v3 = *(const float4*)&Vs[(kk + 3) * 68 + tx * 4];
            #pragma unroll
            for (int i = 0; i < 4; i++) {
                float4 p = *(const float4*)&Ps[(ty * 4 + i) * 68 + kk];
                o[i][0] = fmaf(p.x, v0.x, fmaf(p.y, v1.x, fmaf(p.z, v2.x, fmaf(p.w, v3.x, o[i][0]))));
                o[i][1] = fmaf(p.x, v0.y, fmaf(p.y, v1.y, fmaf(p.z, v2.y, fmaf(p.w, v3.y, o[i][1]))));
                o[i][2] = fmaf(p.x, v0.z, fmaf(p.y, v1.z, fmaf(p.z, v2.z, fmaf(p.w, v3.z, o[i][2]))));
                o[i][3] = fmaf(p.x, v0.w, fmaf(p.y, v1.w, fmaf(p.z, v2.w, fmaf(p.w, v3.w, o[i][3]))));
            }
        }
    }

    #pragma unroll
    for (int i = 0; i < 4; i++) {
        float inv = 1.0f / l_i[i];
        int qi = qt * 64 + ty * 4 + i;
        float4 r = make_float4(o[i][0] * inv, o[i][1] * inv,
                               o[i][2] * inv, o[i][3] * inv);
        *(float4*)(out + ((size_t)b * TS + qi) * DM + h * HD + tx * 4) = r;
    }
}

// ---------------------------------------------------------------------------
extern "C" void kernel_launch(void* const* d_in, const int* in_sizes, int n_in,
                              void* d_out, int out_size)
{
    const float* x     = (const float*)d_in[0];
    const float* w_qkv = (const float*)d_in[1];
    const float* b_qkv = (const float*)d_in[2];
    const float* w_out = (const float*)d_in[3];
    const float* b_out = (const float*)d_in[4];
    float* out = (float*)d_out;

    float* qkv = nullptr;  float* attn = nullptr;
    __nv_bfloat16 *x3 = nullptr, *a3 = nullptr, *wq3 = nullptr, *wo3 = nullptr;
    cudaGetSymbolAddress((void**)&qkv,  g_qkv);
    cudaGetSymbolAddress((void**)&attn, g_attn);
    cudaGetSymbolAddress((void**)&x3,   g_x3);
    cudaGetSymbolAddress((void**)&a3,   g_a3);
    cudaGetSymbolAddress((void**)&wq3,  g_wqkv3);
    cudaGetSymbolAddress((void**)&wo3,  g_wout3);

    cudaFuncSetAttribute(attn_kernel,
                         cudaFuncAttributeMaxDynamicSharedMemorySize, ATTN_SMEM_BYTES);

    const int M = MROWS;                       // 8192
    const size_t actN = (size_t)M * DM;

    // split inputs / weights
    split_act_kernel<<<(int)(actN / 256), 256>>>(x, x3, DM);
    split_wt_kernel<<<dim3(3 * DM / 32, DM / 32), dim3(32, 32)>>>(w_qkv, wq3, DM, 3 * DM);
    split_wt_kernel<<<dim3(DM / 32, DM / 32), dim3(32, 32)>>>(w_out, wo3, DM, DM);

    // QKV projection (HMMA): [8192 x 3072] = x3 @ wq3^T
    gemm_mma_kernel<<<dim3(3 * DM / 128, M / 128), 256>>>(x3, wq3, b_qkv, qkv, 3 * DM);

    // causal attention (fp32)
    attn_kernel<<<dim3(TS / 64, BB * NH), 256, ATTN_SMEM_BYTES>>>(qkv, attn);

    // split attention output, then out projection (HMMA)
    split_act_kernel<<<(int)(actN / 256), 256>>>(attn, a3, DM);
    gemm_mma_kernel<<<dim3(DM / 128, M / 128), 256>>>(a3, wo3, b_out, out, DM);
}

// round 9
// speedup vs baseline: 1.5415x; 1.5415x over previous
#include <cuda_runtime.h>
#include <cuda_bf16.h>
#include <cstdint>
#include <math.h>

#define DM 1024
#define TS 2048
#define BB 4
#define NH 16
#define HD 64
#define K3 (3*DM)            // split-bf16 expanded K = 3072
#define MROWS (BB*TS)        // 8192
#define NEG_BIG (-1e30f)
// 0.125 (1/sqrt(64)) * log2(e): softmax computed in base 2
#define SC2 0.18033688011112042f

// ---------------------------------------------------------------------------
// Scratch (__device__ globals: allocation-free rule)
// ---------------------------------------------------------------------------
__device__ float g_qkv[(size_t)MROWS * 3 * DM];        // fp32 QKV for attention
__device__ __nv_bfloat16 g_x3[(size_t)MROWS * K3];     // [M, 3K] split x
__device__ __nv_bfloat16 g_a3[(size_t)MROWS * K3];     // [M, 3K] split attn-out
__device__ __nv_bfloat16 g_wqkv3[(size_t)(3*DM) * K3]; // [N, 3K] split w_qkv^T
__device__ __nv_bfloat16 g_wout3[(size_t)DM * K3];     // [N, 3K] split w_out^T

// ---------------------------------------------------------------------------
__device__ __forceinline__ uint32_t smem_u32(const void* p) {
    uint32_t a;
    asm("{ .reg .u64 t; cvta.to.shared.u64 t, %1; cvt.u32.u64 %0, t; }"
        : "=r"(a) : "l"(p));
    return a;
}
#define CP_ASYNC16(sm, gm) \
    asm volatile("cp.async.cg.shared.global [%0], [%1], 16;" :: "r"(sm), "l"(gm))
#define CP_COMMIT() asm volatile("cp.async.commit_group;" ::: "memory")
#define CP_WAIT0()  asm volatile("cp.async.wait_group 0;" ::: "memory")
#define CP_WAIT1()  asm volatile("cp.async.wait_group 1;" ::: "memory")
#define CP_WAIT2()  asm volatile("cp.async.wait_group 2;" ::: "memory")

#define LDSM_X4(r0,r1,r2,r3,addr) \
    asm volatile("ldmatrix.sync.aligned.m8n8.x4.shared.b16 {%0,%1,%2,%3}, [%4];" \
        : "=r"(r0),"=r"(r1),"=r"(r2),"=r"(r3) : "r"(addr))
#define MMA_BF16(d, a, b0, b1) \
    asm volatile("mma.sync.aligned.m16n8k16.row.col.f32.bf16.bf16.f32 " \
        "{%0,%1,%2,%3}, {%4,%5,%6,%7}, {%8,%9}, {%0,%1,%2,%3};" \
        : "+f"((d)[0]), "+f"((d)[1]), "+f"((d)[2]), "+f"((d)[3]) \
        : "r"((a)[0]), "r"((a)[1]), "r"((a)[2]), "r"((a)[3]), "r"(b0), "r"(b1))

// Fast exp2 on the fma/alu pipes (MUFU is the attention bottleneck).
// Valid for x <= ~1; deg-5 poly on f in [-0.5,0.5], rel err ~2e-6.
__device__ __forceinline__ float exp2f_fast(float x) {
    x = fmaxf(x, -110.0f);
    float t = x + 12582912.0f;                    // 1.5*2^23: round to int
    int   i = __float_as_int(t) - 0x4B400000;     // n = round(x)
    float f = x - (t - 12582912.0f);              // f in [-0.5, 0.5]
    float p =              0.0013333558f;
    p = fmaf(p, f, 0.0096181291f);
    p = fmaf(p, f, 0.0555041087f);
    p = fmaf(p, f, 0.2402265070f);
    p = fmaf(p, f, 0.6931471806f);
    p = fmaf(p, f, 1.0f);
    return __int_as_float(__float_as_int(p) + (i << 23));
}

// ---------------------------------------------------------------------------
// Split conversion kernels (bf16 hi/lo, K-concatenated)
// act: [hi | hi | lo]   weightT: [hi | lo | hi]  -> hi*hi + hi*lo + lo*hi
// ---------------------------------------------------------------------------
__global__ __launch_bounds__(256) void split_act_kernel(
    const float* __restrict__ in, __nv_bfloat16* __restrict__ out, int K)
{
    size_t idx = (size_t)blockIdx.x * 256 + threadIdx.x;
    int m = (int)(idx / K);
    int k = (int)(idx % K);
    float a = in[idx];
    __nv_bfloat16 hi = __float2bfloat16(a);
    __nv_bfloat16 lo = __float2bfloat16(a - __bfloat162float(hi));
    size_t base = (size_t)m * (3 * K);
    out[base + k]         = hi;
    out[base + K + k]     = hi;
    out[base + 2 * K + k] = lo;
}

__global__ void split_wt_kernel(const float* __restrict__ w,
                                __nv_bfloat16* __restrict__ out, int K, int N)
{
    __shared__ float t[32][33];
    int k0 = blockIdx.y * 32, n0 = blockIdx.x * 32;
    t[threadIdx.y][threadIdx.x] = w[(size_t)(k0 + threadIdx.y) * N + n0 + threadIdx.x];
    __syncthreads();
    float a = t[threadIdx.x][threadIdx.y];      // w[k0+tx][n0+ty]
    int n = n0 + threadIdx.y, k = k0 + threadIdx.x;
    __nv_bfloat16 hi = __float2bfloat16(a);
    __nv_bfloat16 lo = __float2bfloat16(a - __bfloat162float(hi));
    size_t base = (size_t)n * (3 * K);
    out[base + k]         = hi;
    out[base + K + k]     = lo;
    out[base + 2 * K + k] = hi;
}

// ---------------------------------------------------------------------------
// HMMA GEMM: C[M,N] = A[M,K3] @ Bt[N,K3]^T + bias (fp32 out)
// 128x128 CTA tile, BK=32, 8 warps (2x4), warp tile 64x32, mma.m16n8k16.
// 4-stage cp.async ring, ONE barrier per iteration:
//   wait(c) ; barrier ; issue load(c+3) ; compute(c)
// The barrier both publishes stage c (each thread waited its own groups
// before it) and protects buf (c-1)%4 == (c+3)%4 against overwrite.
// ---------------------------------------------------------------------------
#define BK 32
#define SSTR 40                 // smem row stride in bf16
#define NC (K3 / BK)            // 96
#define STAGE_BF (2 * 128 * SSTR)   // bf16 per stage (A then B)
#define GEMM_SMEM (4 * STAGE_BF * 2) // bytes = 81920

__device__ __forceinline__ void stage_load(
    __nv_bfloat16* as, __nv_bfloat16* bs,
    const __nv_bfloat16* __restrict__ A, const __nv_bfloat16* __restrict__ Bt,
    int row0, int col0, int k0, int tid)
{
    #pragma unroll
    for (int j = 0; j < 2; j++) {
        int i = tid + j * 256;          // 0..511
        int r = i >> 2;                 // 0..127
        int u = i & 3;                  // 16B unit (8 bf16)
        uint32_t sa = smem_u32(as + r * SSTR + u * 8);
        CP_ASYNC16(sa, A + (size_t)(row0 + r) * K3 + k0 + u * 8);
        uint32_t sb = smem_u32(bs + r * SSTR + u * 8);
        CP_ASYNC16(sb, Bt + (size_t)(col0 + r) * K3 + k0 + u * 8);
    }
}

__global__ __launch_bounds__(256) void gemm_mma_kernel(
    const __nv_bfloat16* __restrict__ A, const __nv_bfloat16* __restrict__ Bt,
    const float* __restrict__ bias, float* __restrict__ C, int N)
{
    extern __shared__ __align__(16) __nv_bfloat16 smg[];

    const int tid  = threadIdx.x;
    const int lane = tid & 31;
    const int warp = tid >> 5;
    const int wr = warp >> 2;           // 0..1
    const int wc = warp & 3;            // 0..3
    const int m0 = wr * 64;
    const int n0 = wc * 32;
    const int row0 = blockIdx.y * 128;
    const int col0 = blockIdx.x * 128;

    const int lrow  = (lane & 7) + 8 * ((lane >> 3) & 1);  // 0..15
    const int lcol8 = (lane >> 4) * 8;                     // 0 or 8

    float acc[4][4][4];
    #pragma unroll
    for (int mf = 0; mf < 4; mf++)
        #pragma unroll
        for (int nf = 0; nf < 4; nf++)
            #pragma unroll
            for (int e = 0; e < 4; e++) acc[mf][nf][e] = 0.f;

    // prologue: stages 0,1,2 in flight
    #pragma unroll
    for (int s = 0; s < 3; s++) {
        stage_load(smg + s * STAGE_BF, smg + s * STAGE_BF + 128 * SSTR,
                   A, Bt, row0, col0, s * BK, tid);
        CP_COMMIT();
    }

    for (int c = 0; c < NC; c++) {
        // ensure group c complete (per-thread), tail-aware
        if (c + 2 < NC)      { CP_WAIT2(); }
        else if (c + 1 < NC) { CP_WAIT1(); }
        else                 { CP_WAIT0(); }
        __syncthreads();     // publish stage c; buf (c+3)%4 now reusable

        if (c + 3 < NC) {
            int s = (c + 3) & 3;
            stage_load(smg + s * STAGE_BF, smg + s * STAGE_BF + 128 * SSTR,
                       A, Bt, row0, col0, (c + 3) * BK, tid);
            CP_COMMIT();
        }

        const __nv_bfloat16* as = smg + (c & 3) * STAGE_BF;
        const __nv_bfloat16* bs = as + 128 * SSTR;

        #pragma unroll
        for (int ks = 0; ks < 2; ks++) {
            int kb = ks * 16;
            uint32_t af[4][4];
            #pragma unroll
            for (int mf = 0; mf < 4; mf++) {
                uint32_t addr = smem_u32(as + (m0 + mf * 16 + lrow) * SSTR + kb + lcol8);
                LDSM_X4(af[mf][0], af[mf][1], af[mf][2], af[mf][3], addr);
            }
            uint32_t bfr[2][4];
            #pragma unroll
            for (int bp = 0; bp < 2; bp++) {
                uint32_t addr = smem_u32(bs + (n0 + bp * 16 + lrow) * SSTR + kb + lcol8);
                LDSM_X4(bfr[bp][0], bfr[bp][1], bfr[bp][2], bfr[bp][3], addr);
            }
            #pragma unroll
            for (int mf = 0; mf < 4; mf++) {
                #pragma unroll
                for (int nf = 0; nf < 4; nf++) {
                    int bp = nf >> 1, sel = nf & 1;
                    MMA_BF16(acc[mf][nf], af[mf], bfr[bp][sel], bfr[bp][sel + 2]);
                }
            }
        }
    }

    // Epilogue: fp32 + bias
    const int r0l = lane >> 2;          // 0..7
    const int c0l = (lane & 3) * 2;     // 0,2,4,6
    #pragma unroll
    for (int nf = 0; nf < 4; nf++) {
        int col = col0 + n0 + nf * 8 + c0l;
        float2 bv = *(const float2*)(bias + col);
        #pragma unroll
        for (int mf = 0; mf < 4; mf++) {
            int rowA = row0 + m0 + mf * 16 + r0l;
            float2 v0 = make_float2(acc[mf][nf][0] + bv.x, acc[mf][nf][1] + bv.y);
            float2 v1 = make_float2(acc[mf][nf][2] + bv.x, acc[mf][nf][3] + bv.y);
            *(float2*)(C + (size_t)rowA * N + col)       = v0;
            *(float2*)(C + (size_t)(rowA + 8) * N + col) = v1;
        }
    }
}

// ---------------------------------------------------------------------------
// Flash attention (causal, fp32 math, base-2 softmax via exp2f_fast).
// Epilogue writes split-bf16 [hi|hi|lo] directly into a3 (fused split).
// ---------------------------------------------------------------------------
__device__ __forceinline__ float redmax16(float v) {
    v = fmaxf(v, __shfl_xor_sync(0xffffffffu, v, 1));
    v = fmaxf(v, __shfl_xor_sync(0xffffffffu, v, 2));
    v = fmaxf(v, __shfl_xor_sync(0xffffffffu, v, 4));
    v = fmaxf(v, __shfl_xor_sync(0xffffffffu, v, 8));
    return v;
}
__device__ __forceinline__ float redsum16(float v) {
    v += __shfl_xor_sync(0xffffffffu, v, 1);
    v += __shfl_xor_sync(0xffffffffu, v, 2);
    v += __shfl_xor_sync(0xffffffffu, v, 4);
    v += __shfl_xor_sync(0xffffffffu, v, 8);
    return v;
}

#define ATTN_SMEM_FLOATS (64*64 + 64*64 + 64*68 + 64*68)
#define ATTN_SMEM_BYTES  (ATTN_SMEM_FLOATS * 4)

__global__ __launch_bounds__(256) void attn_kernel(
    const float* __restrict__ qkv, __nv_bfloat16* __restrict__ a3)
{
    extern __shared__ __align__(16) float sm[];
    float* Qs = sm;                      // [d][qi]  stride 64 (transposed)
    float* Ks = sm + 4096;               // [d][kj]  stride 64 (transposed)
    float* Vs = sm + 8192;               // [kj][d]  stride 68
    float* Ps = sm + 8192 + 64 * 68;     // [qi][kj] stride 68

    const int tid = threadIdx.x;
    const int tx  = tid & 15;
    const int ty  = tid >> 4;
    const int qt  = blockIdx.x;
    const int b   = blockIdx.y >> 4;
    const int h   = blockIdx.y & 15;

    const int lr = tid >> 2;
    const int lc = tid & 3;

    const float* qbase = qkv + ((size_t)b * TS + (size_t)qt * 64) * (3 * DM) + h * HD;

    #pragma unroll
    for (int cc = 0; cc < 4; cc++) {
        int c = (lc + cc * 4) * 4;
        float4 v = *(const float4*)(qbase + (size_t)lr * (3 * DM) + c);
        Qs[(c + 0) * 64 + lr] = v.x;
        Qs[(c + 1) * 64 + lr] = v.y;
        Qs[(c + 2) * 64 + lr] = v.z;
        Qs[(c + 3) * 64 + lr] = v.w;
    }

    float o[4][4];
    float m_i[4], l_i[4];
    #pragma unroll
    for (int i = 0; i < 4; i++) {
        m_i[i] = NEG_BIG; l_i[i] = 0.f;
        #pragma unroll
        for (int j = 0; j < 4; j++) o[i][j] = 0.f;
    }

    for (int kt = 0; kt <= qt; kt++) {
        __syncthreads();
        const float* kbase = qkv + ((size_t)b * TS + (size_t)kt * 64) * (3 * DM) + DM + h * HD;
        const float* vbase = kbase + DM;
        #pragma unroll
        for (int cc = 0; cc < 4; cc++) {
            int c = (lc + cc * 4) * 4;
            float4 kv = *(const float4*)(kbase + (size_t)lr * (3 * DM) + c);
            Ks[(c + 0) * 64 + lr] = kv.x;
            Ks[(c + 1) * 64 + lr] = kv.y;
            Ks[(c + 2) * 64 + lr] = kv.z;
            Ks[(c + 3) * 64 + lr] = kv.w;
            float4 vv = *(const float4*)(vbase + (size_t)lr * (3 * DM) + c);
            *(float4*)&Vs[lr * 68 + c] = vv;
        }
        __syncthreads();

        float s[4][4];
        #pragma unroll
        for (int i = 0; i < 4; i++)
            #pragma unroll
            for (int j = 0; j < 4; j++) s[i][j] = 0.f;

        #pragma unroll 16
        for (int kk = 0; kk < 64; kk++) {
            float4 q4 = *(const float4*)&Qs[kk * 64 + ty * 4];
            float4 k4 = *(const float4*)&Ks[kk * 64 + tx * 4];
            float qa[4] = {q4.x, q4.y, q4.z, q4.w};
            float ka[4] = {k4.x, k4.y, k4.z, k4.w};
            #pragma unroll
            for (int i = 0; i < 4; i++)
                #pragma unroll
                for (int j = 0; j < 4; j++)
                    s[i][j] = fmaf(qa[i], ka[j], s[i][j]);
        }

        // scale into base-2 logit domain; causal mask on diagonal tile
        const bool diag = (kt == qt);
        #pragma unroll
        for (int i = 0; i < 4; i++) {
            #pragma unroll
            for (int j = 0; j < 4; j++) {
                float v = s[i][j] * SC2;
                if (diag && (tx * 4 + j) > (ty * 4 + i)) v = NEG_BIG;
                s[i][j] = v;
            }
        }

        #pragma unroll
        for (int i = 0; i < 4; i++) {
            float mm = fmaxf(fmaxf(s[i][0], s[i][1]), fmaxf(s[i][2], s[i][3]));
            mm = redmax16(mm);
            float mnew  = fmaxf(m_i[i], mm);
            float alpha = exp2f_fast(m_i[i] - mnew);
            m_i[i] = mnew;
            float p0 = exp2f_fast(s[i][0] - mnew);
            float p1 = exp2f_fast(s[i][1] - mnew);
            float p2 = exp2f_fast(s[i][2] - mnew);
            float p3 = exp2f_fast(s[i][3] - mnew);
            float sum = redsum16(p0 + p1 + p2 + p3);
            l_i[i] = l_i[i] * alpha + sum;
            o[i][0] *= alpha; o[i][1] *= alpha; o[i][2] *= alpha; o[i][3] *= alpha;
            *(float4*)&Ps[(ty * 4 + i) * 68 + tx * 4] = make_float4(p0, p1, p2, p3);
        }
        __syncthreads();

        #pragma unroll
        for (int kk = 0; kk < 64; kk += 4) {
            float4 v0 = *(const float4*)&Vs[(kk + 0) * 68 + tx * 4];
            float4 v1 = *(const float4*)&Vs[(kk + 1) * 68 + tx * 4];
            float4 v2 = *(const float4*)&Vs[(kk + 2) * 68 + tx * 4];
            float4 v3 = *(const float4*)&Vs[(kk + 3) * 68 + tx * 4];
            #pragma unroll
            for (int i = 0; i < 4; i++) {
                float4 p = *(const float4*)&Ps[(ty * 4 + i) * 68 + kk];
                o[i][0] = fmaf(p.x, v0.x, fmaf(p.y, v1.x, fmaf(p.z, v2.x, fmaf(p.w, v3.x, o[i][0]))));
                o[i][1] = fmaf(p.x, v0.y, fmaf(p.y, v1.y, fmaf(p.z, v2.y, fmaf(p.w, v3.y, o[i][1]))));
                o[i][2] = fmaf(p.x, v0.z, fmaf(p.y, v1.z, fmaf(p.z, v2.z, fmaf(p.w, v3.z, o[i][2]))));
                o[i][3] = fmaf(p.x, v0.w, fmaf(p.y, v1.w, fmaf(p.z, v2.w, fmaf(p.w, v3.w, o[i][3]))));
            }
        }
    }

    // Fused epilogue: normalize and write split-bf16 [hi|hi|lo] into a3
    #pragma unroll
    for (int i = 0; i < 4; i++) {
        float inv = 1.0f / l_i[i];
        int row = b * TS + qt * 64 + ty * 4 + i;   // global token row
        int col = h * HD + tx * 4;
        size_t base = (size_t)row * K3;

        float v0 = o[i][0] * inv, v1 = o[i][1] * inv;
        float v2 = o[i][2] * inv, v3 = o[i][3] * inv;

        __nv_bfloat16 h0 = __float2bfloat16(v0), h1 = __float2bfloat16(v1);
        __nv_bfloat16 h2 = __float2bfloat16(v2), h3 = __float2bfloat16(v3);
        __nv_bfloat16 l0 = __float2bfloat16(v0 - __bfloat162float(h0));
        __nv_bfloat16 l1 = __float2bfloat16(v1 - __bfloat162float(h1));
        __nv_bfloat16 l2 = __float2bfloat16(v2 - __bfloat162float(h2));
        __nv_bfloat16 l3 = __float2bfloat16(v3 - __bfloat162float(h3));

        __nv_bfloat162 hp0 = __nv_bfloat162(h0, h1), hp1 = __nv_bfloat162(h2, h3);
        __nv_bfloat162 lp0 = __nv_bfloat162(l0, l1), lp1 = __nv_bfloat162(l2, l3);
        uint2 uh, ul;
        uh.x = *(uint32_t*)&hp0; uh.y = *(uint32_t*)&hp1;
        ul.x = *(uint32_t*)&lp0; ul.y = *(uint32_t*)&lp1;

        *(uint2*)(a3 + base + col)          = uh;  // hi
        *(uint2*)(a3 + base + DM + col)     = uh;  // hi
        *(uint2*)(a3 + base + 2 * DM + col) = ul;  // lo
    }
}

// ---------------------------------------------------------------------------
extern "C" void kernel_launch(void* const* d_in, const int* in_sizes, int n_in,
                              void* d_out, int out_size)
{
    const float* x     = (const float*)d_in[0];
    const float* w_qkv = (const float*)d_in[1];
    const float* b_qkv = (const float*)d_in[2];
    const float* w_out = (const float*)d_in[3];
    const float* b_out = (const float*)d_in[4];
    float* out = (float*)d_out;

    float* qkv = nullptr;
    __nv_bfloat16 *x3 = nullptr, *a3 = nullptr, *wq3 = nullptr, *wo3 = nullptr;
    cudaGetSymbolAddress((void**)&qkv,  g_qkv);
    cudaGetSymbolAddress((void**)&x3,   g_x3);
    cudaGetSymbolAddress((void**)&a3,   g_a3);
    cudaGetSymbolAddress((void**)&wq3,  g_wqkv3);
    cudaGetSymbolAddress((void**)&wo3,  g_wout3);

    cudaFuncSetAttribute(gemm_mma_kernel,
                         cudaFuncAttributeMaxDynamicSharedMemorySize, GEMM_SMEM);
    cudaFuncSetAttribute(attn_kernel,
                         cudaFuncAttributeMaxDynamicSharedMemorySize, ATTN_SMEM_BYTES);

    const int M = MROWS;                       // 8192
    const size_t actN = (size_t)M * DM;

    // split input / weights
    split_act_kernel<<<(int)(actN / 256), 256>>>(x, x3, DM);
    split_wt_kernel<<<dim3(3 * DM / 32, DM / 32), dim3(32, 32)>>>(w_qkv, wq3, DM, 3 * DM);
    split_wt_kernel<<<dim3(DM / 32, DM / 32), dim3(32, 32)>>>(w_out, wo3, DM, DM);

    // QKV projection (HMMA, 4-stage): [8192 x 3072]
    gemm_mma_kernel<<<dim3(3 * DM / 128, M / 128), 256, GEMM_SMEM>>>(
        x3, wq3, b_qkv, qkv, 3 * DM);

    // causal attention (fp32 + fast exp2, fused split epilogue -> a3)
    attn_kernel<<<dim3(TS / 64, BB * NH), 256, ATTN_SMEM_BYTES>>>(qkv, a3);

    // out projection (HMMA, 4-stage): [8192 x 1024]
    gemm_mma_kernel<<<dim3(DM / 128, M / 128), 256, GEMM_SMEM>>>(
        a3, wo3, b_out, out, DM);
}

// round 10
// speedup vs baseline: 1.8731x; 1.2151x over previous
#include <cuda_runtime.h>
#include <cuda_bf16.h>
#include <cstdint>
#include <math.h>

#define DM 1024
#define TS 2048
#define BB 4
#define NH 16
#define HD 64
#define K3 (3*DM)            // split-bf16 expanded K = 3072
#define MROWS (BB*TS)        // 8192
#define NEG_BIG (-1e30f)
// 0.125 (1/sqrt(64)) * log2(e): softmax computed in base 2
#define SC2 0.18033688011112042f

// ---------------------------------------------------------------------------
// Scratch (__device__ globals: allocation-free rule)
// ---------------------------------------------------------------------------
__device__ float g_qkv[(size_t)MROWS * 3 * DM];        // fp32 QKV
__device__ __nv_bfloat16 g_x3[(size_t)MROWS * K3];     // [M, 3K] split x
__device__ __nv_bfloat16 g_a3[(size_t)MROWS * K3];     // [M, 3K] split attn-out
__device__ __nv_bfloat16 g_wqkv3[(size_t)(3*DM) * K3]; // [N, 3K] split w_qkv^T
__device__ __nv_bfloat16 g_wout3[(size_t)DM * K3];     // [N, 3K] split w_out^T

// ---------------------------------------------------------------------------
__device__ __forceinline__ uint32_t smem_u32(const void* p) {
    uint32_t a;
    asm("{ .reg .u64 t; cvta.to.shared.u64 t, %1; cvt.u32.u64 %0, t; }"
        : "=r"(a) : "l"(p));
    return a;
}
#define CP_ASYNC16(sm, gm) \
    asm volatile("cp.async.cg.shared.global [%0], [%1], 16;" :: "r"(sm), "l"(gm))
#define CP_COMMIT() asm volatile("cp.async.commit_group;" ::: "memory")
#define CP_WAIT0()  asm volatile("cp.async.wait_group 0;" ::: "memory")
#define CP_WAIT1()  asm volatile("cp.async.wait_group 1;" ::: "memory")
#define CP_WAIT2()  asm volatile("cp.async.wait_group 2;" ::: "memory")

#define LDSM_X4(r0,r1,r2,r3,addr) \
    asm volatile("ldmatrix.sync.aligned.m8n8.x4.shared.b16 {%0,%1,%2,%3}, [%4];" \
        : "=r"(r0),"=r"(r1),"=r"(r2),"=r"(r3) : "r"(addr))
#define MMA_BF16(d, a, b0, b1) \
    asm volatile("mma.sync.aligned.m16n8k16.row.col.f32.bf16.bf16.f32 " \
        "{%0,%1,%2,%3}, {%4,%5,%6,%7}, {%8,%9}, {%0,%1,%2,%3};" \
        : "+f"((d)[0]), "+f"((d)[1]), "+f"((d)[2]), "+f"((d)[3]) \
        : "r"((a)[0]), "r"((a)[1]), "r"((a)[2]), "r"((a)[3]), "r"(b0), "r"(b1))

// Fast exp2 on the fma/alu pipes. Valid for x <= ~1; rel err ~2e-6.
__device__ __forceinline__ float exp2f_fast(float x) {
    x = fmaxf(x, -110.0f);
    float t = x + 12582912.0f;
    int   i = __float_as_int(t) - 0x4B400000;
    float f = x - (t - 12582912.0f);
    float p =              0.0013333558f;
    p = fmaf(p, f, 0.0096181291f);
    p = fmaf(p, f, 0.0555041087f);
    p = fmaf(p, f, 0.2402265070f);
    p = fmaf(p, f, 0.6931471806f);
    p = fmaf(p, f, 1.0f);
    return __int_as_float(__float_as_int(p) + (i << 23));
}

__device__ __forceinline__ uint32_t pack2bf(float a, float b) {
    __nv_bfloat162 t = __floats2bfloat162_rn(a, b);
    return *reinterpret_cast<uint32_t*>(&t);
}
__device__ __forceinline__ float bflo(float x) {
    return x - __bfloat162float(__float2bfloat16(x));
}

// ---------------------------------------------------------------------------
// Split conversion kernels
// ---------------------------------------------------------------------------
__global__ __launch_bounds__(256) void split_act_kernel(
    const float* __restrict__ in, __nv_bfloat16* __restrict__ out, int K)
{
    size_t idx = (size_t)blockIdx.x * 256 + threadIdx.x;
    int m = (int)(idx / K);
    int k = (int)(idx % K);
    float a = in[idx];
    __nv_bfloat16 hi = __float2bfloat16(a);
    __nv_bfloat16 lo = __float2bfloat16(a - __bfloat162float(hi));
    size_t base = (size_t)m * (3 * K);
    out[base + k]         = hi;
    out[base + K + k]     = hi;
    out[base + 2 * K + k] = lo;
}

__global__ void split_wt_kernel(const float* __restrict__ w,
                                __nv_bfloat16* __restrict__ out, int K, int N)
{
    __shared__ float t[32][33];
    int k0 = blockIdx.y * 32, n0 = blockIdx.x * 32;
    t[threadIdx.y][threadIdx.x] = w[(size_t)(k0 + threadIdx.y) * N + n0 + threadIdx.x];
    __syncthreads();
    float a = t[threadIdx.x][threadIdx.y];
    int n = n0 + threadIdx.y, k = k0 + threadIdx.x;
    __nv_bfloat16 hi = __float2bfloat16(a);
    __nv_bfloat16 lo = __float2bfloat16(a - __bfloat162float(hi));
    size_t base = (size_t)n * (3 * K);
    out[base + k]         = hi;
    out[base + K + k]     = lo;
    out[base + 2 * K + k] = hi;
}

// ---------------------------------------------------------------------------
// HMMA GEMM (unchanged from R9 — known good, 650us QKV / ~220us proj)
// ---------------------------------------------------------------------------
#define BK 32
#define SSTR 40
#define GNC (K3 / BK)
#define STAGE_BF (2 * 128 * SSTR)
#define GEMM_SMEM (4 * STAGE_BF * 2)

__device__ __forceinline__ void stage_load(
    __nv_bfloat16* as, __nv_bfloat16* bs,
    const __nv_bfloat16* __restrict__ A, const __nv_bfloat16* __restrict__ Bt,
    int row0, int col0, int k0, int tid)
{
    #pragma unroll
    for (int j = 0; j < 2; j++) {
        int i = tid + j * 256;
        int r = i >> 2;
        int u = i & 3;
        uint32_t sa = smem_u32(as + r * SSTR + u * 8);
        CP_ASYNC16(sa, A + (size_t)(row0 + r) * K3 + k0 + u * 8);
        uint32_t sb = smem_u32(bs + r * SSTR + u * 8);
        CP_ASYNC16(sb, Bt + (size_t)(col0 + r) * K3 + k0 + u * 8);
    }
}

__global__ __launch_bounds__(256) void gemm_mma_kernel(
    const __nv_bfloat16* __restrict__ A, const __nv_bfloat16* __restrict__ Bt,
    const float* __restrict__ bias, float* __restrict__ C, int N)
{
    extern __shared__ __align__(16) __nv_bfloat16 smg[];

    const int tid  = threadIdx.x;
    const int lane = tid & 31;
    const int warp = tid >> 5;
    const int wr = warp >> 2;
    const int wc = warp & 3;
    const int m0 = wr * 64;
    const int n0 = wc * 32;
    const int row0 = blockIdx.y * 128;
    const int col0 = blockIdx.x * 128;

    const int lrow  = (lane & 7) + 8 * ((lane >> 3) & 1);
    const int lcol8 = (lane >> 4) * 8;

    float acc[4][4][4];
    #pragma unroll
    for (int mf = 0; mf < 4; mf++)
        #pragma unroll
        for (int nf = 0; nf < 4; nf++)
            #pragma unroll
            for (int e = 0; e < 4; e++) acc[mf][nf][e] = 0.f;

    #pragma unroll
    for (int s = 0; s < 3; s++) {
        stage_load(smg + s * STAGE_BF, smg + s * STAGE_BF + 128 * SSTR,
                   A, Bt, row0, col0, s * BK, tid);
        CP_COMMIT();
    }

    for (int c = 0; c < GNC; c++) {
        if (c + 2 < GNC)      { CP_WAIT2(); }
        else if (c + 1 < GNC) { CP_WAIT1(); }
        else                  { CP_WAIT0(); }
        __syncthreads();

        if (c + 3 < GNC) {
            int s = (c + 3) & 3;
            stage_load(smg + s * STAGE_BF, smg + s * STAGE_BF + 128 * SSTR,
                       A, Bt, row0, col0, (c + 3) * BK, tid);
            CP_COMMIT();
        }

        const __nv_bfloat16* as = smg + (c & 3) * STAGE_BF;
        const __nv_bfloat16* bs = as + 128 * SSTR;

        #pragma unroll
        for (int ks = 0; ks < 2; ks++) {
            int kb = ks * 16;
            uint32_t af[4][4];
            #pragma unroll
            for (int mf = 0; mf < 4; mf++) {
                uint32_t addr = smem_u32(as + (m0 + mf * 16 + lrow) * SSTR + kb + lcol8);
                LDSM_X4(af[mf][0], af[mf][1], af[mf][2], af[mf][3], addr);
            }
            uint32_t bfr[2][4];
            #pragma unroll
            for (int bp = 0; bp < 2; bp++) {
                uint32_t addr = smem_u32(bs + (n0 + bp * 16 + lrow) * SSTR + kb + lcol8);
                LDSM_X4(bfr[bp][0], bfr[bp][1], bfr[bp][2], bfr[bp][3], addr);
            }
            #pragma unroll
            for (int mf = 0; mf < 4; mf++) {
                #pragma unroll
                for (int nf = 0; nf < 4; nf++) {
                    int bp = nf >> 1, sel = nf & 1;
                    MMA_BF16(acc[mf][nf], af[mf], bfr[bp][sel], bfr[bp][sel + 2]);
                }
            }
        }
    }

    const int r0l = lane >> 2;
    const int c0l = (lane & 3) * 2;
    #pragma unroll
    for (int nf = 0; nf < 4; nf++) {
        int col = col0 + n0 + nf * 8 + c0l;
        float2 bv = *(const float2*)(bias + col);
        #pragma unroll
        for (int mf = 0; mf < 4; mf++) {
            int rowA = row0 + m0 + mf * 16 + r0l;
            float2 v0 = make_float2(acc[mf][nf][0] + bv.x, acc[mf][nf][1] + bv.y);
            float2 v1 = make_float2(acc[mf][nf][2] + bv.x, acc[mf][nf][3] + bv.y);
            *(float2*)(C + (size_t)rowA * N + col)       = v0;
            *(float2*)(C + (size_t)(rowA + 8) * N + col) = v1;
        }
    }
}

// ---------------------------------------------------------------------------
// Tensor-core flash attention (causal). BM=BN=64, 128 threads = 4 warps x 16 q.
// S = Q3 @ K3^T over K'=192 (split-bf16, 3 terms). Softmax fp32 in-fragment.
// PV: P stays in registers (C-frag == A-frag layout); 3 passes
// (Phi*Vhi + Phi*Vlo + Plo*Vhi) against transposed V tiles in smem.
// Epilogue writes split-bf16 [hi|hi|lo] directly into a3.
// ---------------------------------------------------------------------------
#define QSTR 200    // Q3/K3 smem row stride (bf16): 400B -> ldmatrix conflict-free
#define VSTR 72     // Vt row stride (bf16): 144B -> conflict-free
#define ATTN2_SMEM ((2*64*QSTR + 2*64*VSTR) * 2)   // 69632 bytes

__device__ __forceinline__ float qmax(float v) {
    v = fmaxf(v, __shfl_xor_sync(0xffffffffu, v, 1));
    v = fmaxf(v, __shfl_xor_sync(0xffffffffu, v, 2));
    return v;
}
__device__ __forceinline__ float qsum(float v) {
    v += __shfl_xor_sync(0xffffffffu, v, 1);
    v += __shfl_xor_sync(0xffffffffu, v, 2);
    return v;
}

__global__ __launch_bounds__(128) void attn_mma_kernel(
    const float* __restrict__ qkv, __nv_bfloat16* __restrict__ a3)
{
    extern __shared__ __align__(16) __nv_bfloat16 smb[];
    __nv_bfloat16* Qs3 = smb;                  // [64][QSTR]  [hi|hi|lo]
    __nv_bfloat16* Ks3 = smb + 64 * QSTR;      // [64][QSTR]  [hi|lo|hi]
    __nv_bfloat16* Vhi = smb + 2 * 64 * QSTR;  // [64 d][VSTR]
    __nv_bfloat16* Vlo = Vhi + 64 * VSTR;

    const int tid  = threadIdx.x;
    const int lane = tid & 31;
    const int warp = tid >> 5;          // 0..3 -> q rows 16*warp..+15
    const int qt   = blockIdx.x;
    const int b    = blockIdx.y >> 4;
    const int h    = blockIdx.y & 15;

    const int lrow  = (lane & 7) + 8 * ((lane >> 3) & 1);
    const int lcol8 = (lane >> 4) * 8;
    const int r  = lane >> 2;           // fragment row 0..7
    const int cq = (lane & 3) * 2;      // fragment col pair base

    const float* qbase = qkv + ((size_t)b * TS + (size_t)qt * 64) * (3 * DM) + h * HD;

    // ---- load + split Q once: Qs3 = [hi|hi|lo] ----
    #pragma unroll
    for (int i = 0; i < 8; i++) {
        int idx = tid + 128 * i;        // 0..1023
        int row = idx >> 4;
        int c4  = (idx & 15) * 4;
        float4 v = *(const float4*)(qbase + (size_t)row * (3 * DM) + c4);
        __nv_bfloat16 h0 = __float2bfloat16(v.x), h1 = __float2bfloat16(v.y);
        __nv_bfloat16 h2 = __float2bfloat16(v.z), h3 = __float2bfloat16(v.w);
        uint2 hi, lo;
        __nv_bfloat162 hp0(h0, h1), hp1(h2, h3);
        hi.x = *(uint32_t*)&hp0; hi.y = *(uint32_t*)&hp1;
        lo.x = pack2bf(v.x - __bfloat162float(h0), v.y - __bfloat162float(h1));
        lo.y = pack2bf(v.z - __bfloat162float(h2), v.w - __bfloat162float(h3));
        __nv_bfloat16* qrow = Qs3 + row * QSTR;
        *(uint2*)(qrow + c4)        = hi;
        *(uint2*)(qrow + 64 + c4)   = hi;
        *(uint2*)(qrow + 128 + c4)  = lo;
    }

    float o[8][4];
    #pragma unroll
    for (int db = 0; db < 8; db++)
        #pragma unroll
        for (int e = 0; e < 4; e++) o[db][e] = 0.f;
    float m0 = NEG_BIG, m8 = NEG_BIG, l0 = 0.f, l8 = 0.f;

    for (int kt = 0; kt <= qt; kt++) {
        __syncthreads();   // previous tile's S/PV reads done

        // ---- convert K tile -> Ks3 = [hi|lo|hi] ----
        const float* kbase = qkv + ((size_t)b * TS + (size_t)kt * 64) * (3 * DM)
                           + DM + h * HD;
        const float* vbase = kbase + DM;
        #pragma unroll
        for (int i = 0; i < 8; i++) {
            int idx = tid + 128 * i;
            int row = idx >> 4;
            int c4  = (idx & 15) * 4;
            float4 v = *(const float4*)(kbase + (size_t)row * (3 * DM) + c4);
            __nv_bfloat16 h0 = __float2bfloat16(v.x), h1 = __float2bfloat16(v.y);
            __nv_bfloat16 h2 = __float2bfloat16(v.z), h3 = __float2bfloat16(v.w);
            uint2 hi, lo;
            __nv_bfloat162 hp0(h0, h1), hp1(h2, h3);
            hi.x = *(uint32_t*)&hp0; hi.y = *(uint32_t*)&hp1;
            lo.x = pack2bf(v.x - __bfloat162float(h0), v.y - __bfloat162float(h1));
            lo.y = pack2bf(v.z - __bfloat162float(h2), v.w - __bfloat162float(h3));
            __nv_bfloat16* krow = Ks3 + row * QSTR;
            *(uint2*)(krow + c4)       = hi;
            *(uint2*)(krow + 64 + c4)  = lo;
            *(uint2*)(krow + 128 + c4) = hi;
        }
        // ---- convert V tile -> Vhi/Vlo transposed [d][k] ----
        #pragma unroll
        for (int i = 0; i < 8; i++) {
            int idx = tid + 128 * i;
            int krow = idx >> 4;
            int c4   = (idx & 15) * 4;
            float4 v = *(const float4*)(vbase + (size_t)krow * (3 * DM) + c4);
            float vv[4] = {v.x, v.y, v.z, v.w};
            #pragma unroll
            for (int j = 0; j < 4; j++) {
                __nv_bfloat16 hv = __float2bfloat16(vv[j]);
                Vhi[(c4 + j) * VSTR + krow] = hv;
                Vlo[(c4 + j) * VSTR + krow] =
                    __float2bfloat16(vv[j] - __bfloat162float(hv));
            }
        }
        __syncthreads();

        // ---- S = Q3 K3^T  (12 k-chunks of 16 over K'=192) ----
        float s[8][4];
        #pragma unroll
        for (int nb = 0; nb < 8; nb++)
            #pragma unroll
            for (int e = 0; e < 4; e++) s[nb][e] = 0.f;

        #pragma unroll
        for (int kc = 0; kc < 12; kc++) {
            uint32_t af[4];
            uint32_t aa = smem_u32(Qs3 + (16 * warp + lrow) * QSTR + kc * 16 + lcol8);
            LDSM_X4(af[0], af[1], af[2], af[3], aa);
            uint32_t bf[4][4];
            #pragma unroll
            for (int bp = 0; bp < 4; bp++) {
                uint32_t ba = smem_u32(Ks3 + (bp * 16 + lrow) * QSTR + kc * 16 + lcol8);
                LDSM_X4(bf[bp][0], bf[bp][1], bf[bp][2], bf[bp][3], ba);
            }
            #pragma unroll
            for (int nb = 0; nb < 8; nb++) {
                int bp = nb >> 1, sel = nb & 1;
                MMA_BF16(s[nb], af, bf[bp][sel], bf[bp][sel + 2]);
            }
        }

        // ---- scale to base-2 + causal mask (diagonal tile only) ----
        const bool diag = (kt == qt);
        #pragma unroll
        for (int nb = 0; nb < 8; nb++) {
            #pragma unroll
            for (int e = 0; e < 4; e++) {
                float v = s[nb][e] * SC2;
                if (diag) {
                    int col  = 8 * nb + cq + (e & 1);
                    int rowl = 16 * warp + r + ((e >> 1) << 3);
                    if (col > rowl) v = NEG_BIG;
                }
                s[nb][e] = v;
            }
        }

        // ---- online softmax (rows r and r+8) ----
        float mm0 = NEG_BIG, mm8 = NEG_BIG;
        #pragma unroll
        for (int nb = 0; nb < 8; nb++) {
            mm0 = fmaxf(mm0, fmaxf(s[nb][0], s[nb][1]));
            mm8 = fmaxf(mm8, fmaxf(s[nb][2], s[nb][3]));
        }
        mm0 = qmax(mm0); mm8 = qmax(mm8);
        float mn0 = fmaxf(m0, mm0), mn8 = fmaxf(m8, mm8);
        float al0 = exp2f_fast(m0 - mn0), al8 = exp2f_fast(m8 - mn8);
        m0 = mn0; m8 = mn8;
        float sum0 = 0.f, sum8 = 0.f;
        #pragma unroll
        for (int nb = 0; nb < 8; nb++) {
            s[nb][0] = exp2f_fast(s[nb][0] - mn0);
            s[nb][1] = exp2f_fast(s[nb][1] - mn0);
            s[nb][2] = exp2f_fast(s[nb][2] - mn8);
            s[nb][3] = exp2f_fast(s[nb][3] - mn8);
            sum0 += s[nb][0] + s[nb][1];
            sum8 += s[nb][2] + s[nb][3];
        }
        sum0 = qsum(sum0); sum8 = qsum(sum8);
        l0 = l0 * al0 + sum0;
        l8 = l8 * al8 + sum8;
        #pragma unroll
        for (int db = 0; db < 8; db++) {
            o[db][0] *= al0; o[db][1] *= al0;
            o[db][2] *= al8; o[db][3] *= al8;
        }

        // ---- PV: P in registers (C-frag -> A-frag), 3 split passes ----
        #pragma unroll
        for (int kc = 0; kc < 4; kc++) {
            int n0b = 2 * kc, n1b = 2 * kc + 1;
            uint32_t ah[4], al_[4];
            ah[0] = pack2bf(s[n0b][0], s[n0b][1]);
            ah[1] = pack2bf(s[n0b][2], s[n0b][3]);
            ah[2] = pack2bf(s[n1b][0], s[n1b][1]);
            ah[3] = pack2bf(s[n1b][2], s[n1b][3]);
            al_[0] = pack2bf(bflo(s[n0b][0]), bflo(s[n0b][1]));
            al_[1] = pack2bf(bflo(s[n0b][2]), bflo(s[n0b][3]));
            al_[2] = pack2bf(bflo(s[n1b][0]), bflo(s[n1b][1]));
            al_[3] = pack2bf(bflo(s[n1b][2]), bflo(s[n1b][3]));

            uint32_t bh[4][4], bl[4][4];
            #pragma unroll
            for (int bp = 0; bp < 4; bp++) {
                uint32_t bah = smem_u32(Vhi + (bp * 16 + lrow) * VSTR + kc * 16 + lcol8);
                LDSM_X4(bh[bp][0], bh[bp][1], bh[bp][2], bh[bp][3], bah);
                uint32_t bal = smem_u32(Vlo + (bp * 16 + lrow) * VSTR + kc * 16 + lcol8);
                LDSM_X4(bl[bp][0], bl[bp][1], bl[bp][2], bl[bp][3], bal);
            }
            #pragma unroll
            for (int db = 0; db < 8; db++) {
                int bp = db >> 1, sel = db & 1;
                MMA_BF16(o[db], ah, bh[bp][sel], bh[bp][sel + 2]);
                MMA_BF16(o[db], ah, bl[bp][sel], bl[bp][sel + 2]);
                MMA_BF16(o[db], al_, bh[bp][sel], bh[bp][sel + 2]);
            }
        }
    }

    // ---- epilogue: normalize + fused split-bf16 [hi|hi|lo] into a3 ----
    float inv0 = 1.0f / l0, inv8 = 1.0f / l8;
    int rowg = qt * 64 + 16 * warp + r;
    size_t base0 = ((size_t)b * TS + rowg) * K3;
    size_t base8 = base0 + (size_t)8 * K3;
    #pragma unroll
    for (int db = 0; db < 8; db++) {
        int col = h * HD + 8 * db + cq;
        float v0 = o[db][0] * inv0, v1 = o[db][1] * inv0;
        float v2 = o[db][2] * inv8, v3 = o[db][3] * inv8;
        uint32_t h0p = pack2bf(v0, v1);
        uint32_t l0p = pack2bf(bflo(v0), bflo(v1));
        uint32_t h8p = pack2bf(v2, v3);
        uint32_t l8p = pack2bf(bflo(v2), bflo(v3));
        *(uint32_t*)(a3 + base0 + col)          = h0p;
        *(uint32_t*)(a3 + base0 + DM + col)     = h0p;
        *(uint32_t*)(a3 + base0 + 2 * DM + col) = l0p;
        *(uint32_t*)(a3 + base8 + col)          = h8p;
        *(uint32_t*)(a3 + base8 + DM + col)     = h8p;
        *(uint32_t*)(a3 + base8 + 2 * DM + col) = l8p;
    }
}

// ---------------------------------------------------------------------------
extern "C" void kernel_launch(void* const* d_in, const int* in_sizes, int n_in,
                              void* d_out, int out_size)
{
    const float* x     = (const float*)d_in[0];
    const float* w_qkv = (const float*)d_in[1];
    const float* b_qkv = (const float*)d_in[2];
    const float* w_out = (const float*)d_in[3];
    const float* b_out = (const float*)d_in[4];
    float* out = (float*)d_out;

    float* qkv = nullptr;
    __nv_bfloat16 *x3 = nullptr, *a3 = nullptr, *wq3 = nullptr, *wo3 = nullptr;
    cudaGetSymbolAddress((void**)&qkv,  g_qkv);
    cudaGetSymbolAddress((void**)&x3,   g_x3);
    cudaGetSymbolAddress((void**)&a3,   g_a3);
    cudaGetSymbolAddress((void**)&wq3,  g_wqkv3);
    cudaGetSymbolAddress((void**)&wo3,  g_wout3);

    cudaFuncSetAttribute(gemm_mma_kernel,
                         cudaFuncAttributeMaxDynamicSharedMemorySize, GEMM_SMEM);
    cudaFuncSetAttribute(attn_mma_kernel,
                         cudaFuncAttributeMaxDynamicSharedMemorySize, ATTN2_SMEM);

    const int M = MROWS;
    const size_t actN = (size_t)M * DM;

    split_act_kernel<<<(int)(actN / 256), 256>>>(x, x3, DM);
    split_wt_kernel<<<dim3(3 * DM / 32, DM / 32), dim3(32, 32)>>>(w_qkv, wq3, DM, 3 * DM);
    split_wt_kernel<<<dim3(DM / 32, DM / 32), dim3(32, 32)>>>(w_out, wo3, DM, DM);

    gemm_mma_kernel<<<dim3(3 * DM / 128, M / 128), 256, GEMM_SMEM>>>(
        x3, wq3, b_qkv, qkv, 3 * DM);

    attn_mma_kernel<<<dim3(TS / 64, BB * NH), 128, ATTN2_SMEM>>>(qkv, a3);

    gemm_mma_kernel<<<dim3(DM / 128, M / 128), 256, GEMM_SMEM>>>(
        a3, wo3, b_out, out, DM);
}

// round 13
// speedup vs baseline: 2.4637x; 1.3153x over previous
#include <cuda_runtime.h>
#include <cuda_bf16.h>
#include <cstdint>
#include <math.h>

#define DM 1024
#define TS 2048
#define BB 4
#define NH 16
#define HD 64
#define K3 (3*DM)            // split-bf16 expanded K = 3072
#define MROWS (BB*TS)        // 8192
#define NEG_BIG (-1e30f)
#define SC2 0.18033688011112042f   // 0.125 * log2(e)

// ---------------------------------------------------------------------------
// Scratch
// ---------------------------------------------------------------------------
__device__ float g_qkv[(size_t)MROWS * 3 * DM];          // fp32 QKV
__device__ __nv_bfloat16 g_x3[(size_t)MROWS * K3];       // [M,3K] split x
__device__ __nv_bfloat16 g_a3[(size_t)MROWS * K3];       // [M,3K] split attn-out
__device__ __nv_bfloat16 g_wqkv3[(size_t)(3*DM) * K3];   // [N,3K] split w_qkv^T
__device__ __nv_bfloat16 g_wout3[(size_t)DM * K3];       // [N,3K] split w_out^T
__device__ __nv_bfloat16 g_k2[(size_t)BB*NH*TS*128];     // K split [hi|lo] per (b,h,t)
__device__ __nv_bfloat16 g_vt[(size_t)BB*NH*128*TS];     // V^T: rows 0-63 hi, 64-127 lo

// ---------------------------------------------------------------------------
__device__ __forceinline__ uint32_t smem_u32(const void* p) {
    uint32_t a;
    asm("{ .reg .u64 t; cvta.to.shared.u64 t, %1; cvt.u32.u64 %0, t; }"
        : "=r"(a) : "l"(p));
    return a;
}
#define CP_ASYNC16(sm, gm) \
    asm volatile("cp.async.cg.shared.global [%0], [%1], 16;" :: "r"(sm), "l"(gm))
#define CP_COMMIT() asm volatile("cp.async.commit_group;" ::: "memory")
#define CP_WAIT0()  asm volatile("cp.async.wait_group 0;" ::: "memory")
#define CP_WAIT1()  asm volatile("cp.async.wait_group 1;" ::: "memory")
#define CP_WAIT2()  asm volatile("cp.async.wait_group 2;" ::: "memory")

#define LDSM_X4(r0,r1,r2,r3,addr) \
    asm volatile("ldmatrix.sync.aligned.m8n8.x4.shared.b16 {%0,%1,%2,%3}, [%4];" \
        : "=r"(r0),"=r"(r1),"=r"(r2),"=r"(r3) : "r"(addr))
#define MMA_BF16(d, a, b0, b1) \
    asm volatile("mma.sync.aligned.m16n8k16.row.col.f32.bf16.bf16.f32 " \
        "{%0,%1,%2,%3}, {%4,%5,%6,%7}, {%8,%9}, {%0,%1,%2,%3};" \
        : "+f"((d)[0]), "+f"((d)[1]), "+f"((d)[2]), "+f"((d)[3]) \
        : "r"((a)[0]), "r"((a)[1]), "r"((a)[2]), "r"((a)[3]), "r"(b0), "r"(b1))

__device__ __forceinline__ float exp2f_fast(float x) {
    x = fmaxf(x, -110.0f);
    float t = x + 12582912.0f;
    int   i = __float_as_int(t) - 0x4B400000;
    float f = x - (t - 12582912.0f);
    float p =              0.0013333558f;
    p = fmaf(p, f, 0.0096181291f);
    p = fmaf(p, f, 0.0555041087f);
    p = fmaf(p, f, 0.2402265070f);
    p = fmaf(p, f, 0.6931471806f);
    p = fmaf(p, f, 1.0f);
    return __int_as_float(__float_as_int(p) + (i << 23));
}
__device__ __forceinline__ uint32_t pack2bf(float a, float b) {
    __nv_bfloat162 t = __floats2bfloat162_rn(a, b);
    return *reinterpret_cast<uint32_t*>(&t);
}
__device__ __forceinline__ float bflo(float x) {
    return x - __bfloat162float(__float2bfloat16(x));
}

// ---------------------------------------------------------------------------
// Split conversion kernels (projection GEMM inputs)
// ---------------------------------------------------------------------------
__global__ __launch_bounds__(256) void split_act_kernel(
    const float* __restrict__ in, __nv_bfloat16* __restrict__ out, int K)
{
    size_t idx = (size_t)blockIdx.x * 256 + threadIdx.x;
    int m = (int)(idx / K);
    int k = (int)(idx % K);
    float a = in[idx];
    __nv_bfloat16 hi = __float2bfloat16(a);
    __nv_bfloat16 lo = __float2bfloat16(a - __bfloat162float(hi));
    size_t base = (size_t)m * (3 * K);
    out[base + k]         = hi;
    out[base + K + k]     = hi;
    out[base + 2 * K + k] = lo;
}

__global__ void split_wt_kernel(const float* __restrict__ w,
                                __nv_bfloat16* __restrict__ out, int K, int N)
{
    __shared__ float t[32][33];
    int k0 = blockIdx.y * 32, n0 = blockIdx.x * 32;
    t[threadIdx.y][threadIdx.x] = w[(size_t)(k0 + threadIdx.y) * N + n0 + threadIdx.x];
    __syncthreads();
    float a = t[threadIdx.x][threadIdx.y];
    int n = n0 + threadIdx.y, k = k0 + threadIdx.x;
    __nv_bfloat16 hi = __float2bfloat16(a);
    __nv_bfloat16 lo = __float2bfloat16(a - __bfloat162float(hi));
    size_t base = (size_t)n * (3 * K);
    out[base + k]         = hi;
    out[base + K + k]     = lo;
    out[base + 2 * K + k] = hi;
}

// ---------------------------------------------------------------------------
// K/V pre-split: K -> gk2 [t][hi(64)|lo(64)], V -> gvt transposed [d][t]
// (rows 0-63 = hi, rows 64-127 = lo), per (b,h).
// ---------------------------------------------------------------------------
__global__ __launch_bounds__(256) void kv_split_kernel(
    const float* __restrict__ qkv, __nv_bfloat16* __restrict__ gk2,
    __nv_bfloat16* __restrict__ gvt)
{
    __shared__ float sv[64 * 68];
    const int t0 = blockIdx.x * 64;
    const int bh = blockIdx.y;
    const int b = bh >> 4, h = bh & 15;
    const int tid = threadIdx.x;
    const float* kbase = qkv + ((size_t)b * TS + t0) * (3 * DM) + DM + h * HD;
    const float* vbase = kbase + DM;

    #pragma unroll
    for (int i = 0; i < 4; i++) {
        int idx = tid + 256 * i;        // 0..1023
        int row = idx >> 4, c4 = (idx & 15) * 4;
        float4 v = *(const float4*)(kbase + (size_t)row * (3 * DM) + c4);
        uint2 hi, lo;
        hi.x = pack2bf(v.x, v.y);           hi.y = pack2bf(v.z, v.w);
        lo.x = pack2bf(bflo(v.x), bflo(v.y)); lo.y = pack2bf(bflo(v.z), bflo(v.w));
        __nv_bfloat16* krow = gk2 + ((size_t)bh * TS + t0 + row) * 128;
        *(uint2*)(krow + c4)      = hi;
        *(uint2*)(krow + 64 + c4) = lo;
        float4 vv = *(const float4*)(vbase + (size_t)row * (3 * DM) + c4);
        *(float4*)(sv + row * 68 + c4) = vv;
    }
    __syncthreads();

    const int d = tid & 63, q = tid >> 6;        // q in 0..3: 16 tokens each
    __align__(16) __nv_bfloat16 hbuf[16], lbuf[16];
    #pragma unroll
    for (int tt = 0; tt < 16; tt++) {
        float f = sv[(q * 16 + tt) * 68 + d];
        __nv_bfloat16 hv = __float2bfloat16(f);
        hbuf[tt] = hv;
        lbuf[tt] = __float2bfloat16(f - __bfloat162float(hv));
    }
    size_t hrow = ((size_t)bh * 128 + d) * TS + t0 + q * 16;
    size_t lrow = ((size_t)bh * 128 + 64 + d) * TS + t0 + q * 16;
    *(uint4*)(gvt + hrow)     = *(uint4*)hbuf;
    *(uint4*)(gvt + hrow + 8) = *(uint4*)(hbuf + 8);
    *(uint4*)(gvt + lrow)     = *(uint4*)lbuf;
    *(uint4*)(gvt + lrow + 8) = *(uint4*)(lbuf + 8);
}

// ---------------------------------------------------------------------------
// HMMA GEMM v3: 128x128 CTA tile, 4 warps (2x2) of 64x64, BK=32,
// 4-stage cp.async ring, one barrier/iter. 128 threads, 2 CTAs/SM.
// ---------------------------------------------------------------------------
#define BK 32
#define SSTR 40
#define GNC (K3 / BK)
#define STAGE_BF (2 * 128 * SSTR)
#define GEMM_SMEM (4 * STAGE_BF * 2)

__device__ __forceinline__ void stage_load(
    __nv_bfloat16* as, __nv_bfloat16* bs,
    const __nv_bfloat16* __restrict__ A, const __nv_bfloat16* __restrict__ Bt,
    int row0, int col0, int k0, int tid)
{
    #pragma unroll
    for (int j = 0; j < 4; j++) {
        int i = tid + j * 128;          // 0..511
        int r = i >> 2;
        int u = i & 3;
        uint32_t sa = smem_u32(as + r * SSTR + u * 8);
        CP_ASYNC16(sa, A + (size_t)(row0 + r) * K3 + k0 + u * 8);
        uint32_t sb = smem_u32(bs + r * SSTR + u * 8);
        CP_ASYNC16(sb, Bt + (size_t)(col0 + r) * K3 + k0 + u * 8);
    }
}

__global__ __launch_bounds__(128, 2) void gemm_mma_kernel(
    const __nv_bfloat16* __restrict__ A, const __nv_bfloat16* __restrict__ Bt,
    const float* __restrict__ bias, float* __restrict__ C, int N)
{
    extern __shared__ __align__(16) __nv_bfloat16 smg[];

    const int tid  = threadIdx.x;
    const int lane = tid & 31;
    const int warp = tid >> 5;          // 4 warps: 2x2
    const int m0 = (warp >> 1) * 64;
    const int n0 = (warp & 1) * 64;
    const int row0 = blockIdx.y * 128;
    const int col0 = blockIdx.x * 128;

    const int lrow  = (lane & 7) + 8 * ((lane >> 3) & 1);
    const int lcol8 = (lane >> 4) * 8;

    float acc[4][8][4];
    #pragma unroll
    for (int mf = 0; mf < 4; mf++)
        #pragma unroll
        for (int nf = 0; nf < 8; nf++)
            #pragma unroll
            for (int e = 0; e < 4; e++) acc[mf][nf][e] = 0.f;

    #pragma unroll
    for (int s = 0; s < 3; s++) {
        stage_load(smg + s * STAGE_BF, smg + s * STAGE_BF + 128 * SSTR,
                   A, Bt, row0, col0, s * BK, tid);
        CP_COMMIT();
    }

    for (int c = 0; c < GNC; c++) {
        if (c + 2 < GNC)      { CP_WAIT2(); }
        else if (c + 1 < GNC) { CP_WAIT1(); }
        else                  { CP_WAIT0(); }
        __syncthreads();

        if (c + 3 < GNC) {
            int s = (c + 3) & 3;
            stage_load(smg + s * STAGE_BF, smg + s * STAGE_BF + 128 * SSTR,
                       A, Bt, row0, col0, (c + 3) * BK, tid);
            CP_COMMIT();
        }

        const __nv_bfloat16* as = smg + (c & 3) * STAGE_BF;
        const __nv_bfloat16* bs = as + 128 * SSTR;

        #pragma unroll
        for (int ks = 0; ks < 2; ks++) {
            int kb = ks * 16;
            uint32_t af[4][4];
            #pragma unroll
            for (int mf = 0; mf < 4; mf++) {
                uint32_t addr = smem_u32(as + (m0 + mf * 16 + lrow) * SSTR + kb + lcol8);
                LDSM_X4(af[mf][0], af[mf][1], af[mf][2], af[mf][3], addr);
            }
            uint32_t bfr[4][4];
            #pragma unroll
            for (int np = 0; np < 4; np++) {
                uint32_t addr = smem_u32(bs + (n0 + np * 16 + lrow) * SSTR + kb + lcol8);
                LDSM_X4(bfr[np][0], bfr[np][1], bfr[np][2], bfr[np][3], addr);
            }
            #pragma unroll
            for (int mf = 0; mf < 4; mf++) {
                #pragma unroll
                for (int nf = 0; nf < 8; nf++) {
                    int bp = nf >> 1, sel = nf & 1;
                    MMA_BF16(acc[mf][nf], af[mf], bfr[bp][sel], bfr[bp][sel + 2]);
                }
            }
        }
    }

    const int r0l = lane >> 2;
    const int c0l = (lane & 3) * 2;
    #pragma unroll
    for (int nf = 0; nf < 8; nf++) {
        int col = col0 + n0 + nf * 8 + c0l;
        float2 bv = *(const float2*)(bias + col);
        #pragma unroll
        for (int mf = 0; mf < 4; mf++) {
            int rowA = row0 + m0 + mf * 16 + r0l;
            float2 v0 = make_float2(acc[mf][nf][0] + bv.x, acc[mf][nf][1] + bv.y);
            float2 v1 = make_float2(acc[mf][nf][2] + bv.x, acc[mf][nf][3] + bv.y);
            *(float2*)(C + (size_t)rowA * N + col)       = v0;
            *(float2*)(C + (size_t)(rowA + 8) * N + col) = v1;
        }
    }
}

// ---------------------------------------------------------------------------
// Tensor-core flash attention v2: pre-split K/V streamed via cp.async
// double buffering. BM=BN=64, 128 threads.
// ---------------------------------------------------------------------------
#define QKSTR 136   // [hi|lo] row stride (272B: conflict-free ldmatrix)
#define VSTR  72    // V^T row stride (144B: conflict-free)
#define ATTN2_SMEM ((64*QKSTR + 2*64*QKSTR + 2*128*VSTR) * 2)

__device__ __forceinline__ float qmax(float v) {
    v = fmaxf(v, __shfl_xor_sync(0xffffffffu, v, 1));
    v = fmaxf(v, __shfl_xor_sync(0xffffffffu, v, 2));
    return v;
}
__device__ __forceinline__ float qsum(float v) {
    v += __shfl_xor_sync(0xffffffffu, v, 1);
    v += __shfl_xor_sync(0xffffffffu, v, 2);
    return v;
}

__device__ __forceinline__ void attn_stage_load(
    __nv_bfloat16* kdst, __nv_bfloat16* vdst,
    const __nv_bfloat16* __restrict__ gk2, const __nv_bfloat16* __restrict__ gvt,
    int bh, int kt, int tid)
{
    // K tile: 64 rows x 128 bf16 ([hi|lo]) = 1024 16B units  (R11 bug: was 512)
    const __nv_bfloat16* ksrc = gk2 + ((size_t)bh * TS + kt * 64) * 128;
    #pragma unroll
    for (int j = 0; j < 8; j++) {
        int i = tid + 128 * j;          // 0..1023
        int r = i >> 4, u = i & 15;     // r 0..63, u 0..15 (full 128 bf16/row)
        CP_ASYNC16(smem_u32(kdst + r * QKSTR + u * 8), ksrc + r * 128 + u * 8);
    }
    // V tile: 128 rows x 64 bf16 = 1024 16B units
    const __nv_bfloat16* vsrc = gvt + (size_t)bh * 128 * TS + kt * 64;
    #pragma unroll
    for (int j = 0; j < 8; j++) {
        int i = tid + 128 * j;          // 0..1023
        int vr = i >> 3, u = i & 7;     // vr 0..127, u 0..7
        CP_ASYNC16(smem_u32(vdst + vr * VSTR + u * 8),
                   vsrc + (size_t)vr * TS + u * 8);
    }
}

__global__ __launch_bounds__(128) void attn_mma_kernel(
    const float* __restrict__ qkv, const __nv_bfloat16* __restrict__ gk2,
    const __nv_bfloat16* __restrict__ gvt, __nv_bfloat16* __restrict__ a3)
{
    extern __shared__ __align__(16) __nv_bfloat16 smb[];
    __nv_bfloat16* Qs  = smb;                         // [64][136]
    __nv_bfloat16* Kst = smb + 64 * QKSTR;            // [2][64][136]
    __nv_bfloat16* Vst = smb + 3 * 64 * QKSTR;        // [2][128][72]

    const int tid  = threadIdx.x;
    const int lane = tid & 31;
    const int warp = tid >> 5;
    const int qt   = blockIdx.x;
    const int bh   = blockIdx.y;
    const int b    = bh >> 4, h = bh & 15;

    const int lrow  = (lane & 7) + 8 * ((lane >> 3) & 1);
    const int lcol8 = (lane >> 4) * 8;
    const int r  = lane >> 2;
    const int cq = (lane & 3) * 2;

    // ---- Q load + split [hi|lo] ----
    const float* qbase = qkv + ((size_t)b * TS + (size_t)qt * 64) * (3 * DM) + h * HD;
    #pragma unroll
    for (int i = 0; i < 8; i++) {
        int idx = tid + 128 * i;
        int row = idx >> 4;
        int c4  = (idx & 15) * 4;
        float4 v = *(const float4*)(qbase + (size_t)row * (3 * DM) + c4);
        uint2 hi, lo;
        hi.x = pack2bf(v.x, v.y);             hi.y = pack2bf(v.z, v.w);
        lo.x = pack2bf(bflo(v.x), bflo(v.y)); lo.y = pack2bf(bflo(v.z), bflo(v.w));
        __nv_bfloat16* qrow = Qs + row * QKSTR;
        *(uint2*)(qrow + c4)      = hi;
        *(uint2*)(qrow + 64 + c4) = lo;
    }

    float o[8][4];
    #pragma unroll
    for (int db = 0; db < 8; db++)
        #pragma unroll
        for (int e = 0; e < 4; e++) o[db][e] = 0.f;
    float m0 = NEG_BIG, m8 = NEG_BIG, l0 = 0.f, l8 = 0.f;

    attn_stage_load(Kst, Vst, gk2, gvt, bh, 0, tid);
    CP_COMMIT();

    for (int kt = 0; kt <= qt; kt++) {
        CP_WAIT0();
        __syncthreads();

        if (kt < qt) {
            int s = (kt + 1) & 1;
            attn_stage_load(Kst + s * 64 * QKSTR, Vst + s * 128 * VSTR,
                            gk2, gvt, bh, kt + 1, tid);
            CP_COMMIT();
        }

        const __nv_bfloat16* Kcur = Kst + (kt & 1) * 64 * QKSTR;
        const __nv_bfloat16* Vcur = Vst + (kt & 1) * 128 * VSTR;

        // ---- S = Qhi·Khi + Qhi·Klo + Qlo·Khi ----
        float s[8][4];
        #pragma unroll
        for (int nb = 0; nb < 8; nb++)
            #pragma unroll
            for (int e = 0; e < 4; e++) s[nb][e] = 0.f;

        #pragma unroll
        for (int kc = 0; kc < 4; kc++) {
            uint32_t ah[4], alo[4];
            uint32_t qa = smem_u32(Qs + (16 * warp + lrow) * QKSTR + kc * 16 + lcol8);
            LDSM_X4(ah[0], ah[1], ah[2], ah[3], qa);
            uint32_t qa2 = smem_u32(Qs + (16 * warp + lrow) * QKSTR + 64 + kc * 16 + lcol8);
            LDSM_X4(alo[0], alo[1], alo[2], alo[3], qa2);
            uint32_t bh_[4][4], bl_[4][4];
            #pragma unroll
            for (int np = 0; np < 4; np++) {
                uint32_t ka = smem_u32(Kcur + (np * 16 + lrow) * QKSTR + kc * 16 + lcol8);
                LDSM_X4(bh_[np][0], bh_[np][1], bh_[np][2], bh_[np][3], ka);
                uint32_t ka2 = smem_u32(Kcur + (np * 16 + lrow) * QKSTR + 64 + kc * 16 + lcol8);
                LDSM_X4(bl_[np][0], bl_[np][1], bl_[np][2], bl_[np][3], ka2);
            }
            #pragma unroll
            for (int nb = 0; nb < 8; nb++) {
                int bp = nb >> 1, sel = nb & 1;
                MMA_BF16(s[nb], ah,  bh_[bp][sel], bh_[bp][sel + 2]);
                MMA_BF16(s[nb], ah,  bl_[bp][sel], bl_[bp][sel + 2]);
                MMA_BF16(s[nb], alo, bh_[bp][sel], bh_[bp][sel + 2]);
            }
        }

        // ---- scale + causal mask ----
        const bool diag = (kt == qt);
        #pragma unroll
        for (int nb = 0; nb < 8; nb++) {
            #pragma unroll
            for (int e = 0; e < 4; e++) {
                float v = s[nb][e] * SC2;
                if (diag) {
                    int col  = 8 * nb + cq + (e & 1);
                    int rowl = 16 * warp + r + ((e >> 1) << 3);
                    if (col > rowl) v = NEG_BIG;
                }
                s[nb][e] = v;
            }
        }

        // ---- online softmax ----
        float mm0 = NEG_BIG, mm8 = NEG_BIG;
        #pragma unroll
        for (int nb = 0; nb < 8; nb++) {
            mm0 = fmaxf(mm0, fmaxf(s[nb][0], s[nb][1]));
            mm8 = fmaxf(mm8, fmaxf(s[nb][2], s[nb][3]));
        }
        mm0 = qmax(mm0); mm8 = qmax(mm8);
        float mn0 = fmaxf(m0, mm0), mn8 = fmaxf(m8, mm8);
        float al0 = exp2f_fast(m0 - mn0), al8 = exp2f_fast(m8 - mn8);
        m0 = mn0; m8 = mn8;
        float sum0 = 0.f, sum8 = 0.f;
        #pragma unroll
        for (int nb = 0; nb < 8; nb++) {
            s[nb][0] = exp2f_fast(s[nb][0] - mn0);
            s[nb][1] = exp2f_fast(s[nb][1] - mn0);
            s[nb][2] = exp2f_fast(s[nb][2] - mn8);
            s[nb][3] = exp2f_fast(s[nb][3] - mn8);
            sum0 += s[nb][0] + s[nb][1];
            sum8 += s[nb][2] + s[nb][3];
        }
        sum0 = qsum(sum0); sum8 = qsum(sum8);
        l0 = l0 * al0 + sum0;
        l8 = l8 * al8 + sum8;
        #pragma unroll
        for (int db = 0; db < 8; db++) {
            o[db][0] *= al0; o[db][1] *= al0;
            o[db][2] *= al8; o[db][3] *= al8;
        }

        // ---- PV (P in registers; 3 split passes) ----
        #pragma unroll
        for (int kc = 0; kc < 4; kc++) {
            int n0b = 2 * kc, n1b = 2 * kc + 1;
            uint32_t ph[4], pl[4];
            ph[0] = pack2bf(s[n0b][0], s[n0b][1]);
            ph[1] = pack2bf(s[n0b][2], s[n0b][3]);
            ph[2] = pack2bf(s[n1b][0], s[n1b][1]);
            ph[3] = pack2bf(s[n1b][2], s[n1b][3]);
            pl[0] = pack2bf(bflo(s[n0b][0]), bflo(s[n0b][1]));
            pl[1] = pack2bf(bflo(s[n0b][2]), bflo(s[n0b][3]));
            pl[2] = pack2bf(bflo(s[n1b][0]), bflo(s[n1b][1]));
            pl[3] = pack2bf(bflo(s[n1b][2]), bflo(s[n1b][3]));

            uint32_t vh[4][4], vl[4][4];
            #pragma unroll
            for (int bp = 0; bp < 4; bp++) {
                uint32_t va = smem_u32(Vcur + (bp * 16 + lrow) * VSTR + kc * 16 + lcol8);
                LDSM_X4(vh[bp][0], vh[bp][1], vh[bp][2], vh[bp][3], va);
                uint32_t va2 = smem_u32(Vcur + (64 + bp * 16 + lrow) * VSTR + kc * 16 + lcol8);
                LDSM_X4(vl[bp][0], vl[bp][1], vl[bp][2], vl[bp][3], va2);
            }
            #pragma unroll
            for (int db = 0; db < 8; db++) {
                int bp = db >> 1, sel = db & 1;
                MMA_BF16(o[db], ph, vh[bp][sel], vh[bp][sel + 2]);
                MMA_BF16(o[db], ph, vl[bp][sel], vl[bp][sel + 2]);
                MMA_BF16(o[db], pl, vh[bp][sel], vh[bp][sel + 2]);
            }
        }
    }

    // ---- epilogue: normalize + split-bf16 [hi|hi|lo] into a3 ----
    float inv0 = 1.0f / l0, inv8 = 1.0f / l8;
    int rowg = qt * 64 + 16 * warp + r;
    size_t base0 = ((size_t)b * TS + rowg) * K3;
    size_t base8 = base0 + (size_t)8 * K3;
    #pragma unroll
    for (int db = 0; db < 8; db++) {
        int col = h * HD + 8 * db + cq;
        float v0 = o[db][0] * inv0, v1 = o[db][1] * inv0;
        float v2 = o[db][2] * inv8, v3 = o[db][3] * inv8;
        uint32_t h0p = pack2bf(v0, v1);
        uint32_t l0p = pack2bf(bflo(v0), bflo(v1));
        uint32_t h8p = pack2bf(v2, v3);
        uint32_t l8p = pack2bf(bflo(v2), bflo(v3));
        *(uint32_t*)(a3 + base0 + col)          = h0p;
        *(uint32_t*)(a3 + base0 + DM + col)     = h0p;
        *(uint32_t*)(a3 + base0 + 2 * DM + col) = l0p;
        *(uint32_t*)(a3 + base8 + col)          = h8p;
        *(uint32_t*)(a3 + base8 + DM + col)     = h8p;
        *(uint32_t*)(a3 + base8 + 2 * DM + col) = l8p;
    }
}

// ---------------------------------------------------------------------------
extern "C" void kernel_launch(void* const* d_in, const int* in_sizes, int n_in,
                              void* d_out, int out_size)
{
    const float* x     = (const float*)d_in[0];
    const float* w_qkv = (const float*)d_in[1];
    const float* b_qkv = (const float*)d_in[2];
    const float* w_out = (const float*)d_in[3];
    const float* b_out = (const float*)d_in[4];
    float* out = (float*)d_out;

    float* qkv = nullptr;
    __nv_bfloat16 *x3 = nullptr, *a3 = nullptr, *wq3 = nullptr, *wo3 = nullptr;
    __nv_bfloat16 *k2 = nullptr, *vt = nullptr;
    cudaGetSymbolAddress((void**)&qkv, g_qkv);
    cudaGetSymbolAddress((void**)&x3,  g_x3);
    cudaGetSymbolAddress((void**)&a3,  g_a3);
    cudaGetSymbolAddress((void**)&wq3, g_wqkv3);
    cudaGetSymbolAddress((void**)&wo3, g_wout3);
    cudaGetSymbolAddress((void**)&k2,  g_k2);
    cudaGetSymbolAddress((void**)&vt,  g_vt);

    cudaFuncSetAttribute(gemm_mma_kernel,
                         cudaFuncAttributeMaxDynamicSharedMemorySize, GEMM_SMEM);
    cudaFuncSetAttribute(attn_mma_kernel,
                         cudaFuncAttributeMaxDynamicSharedMemorySize, ATTN2_SMEM);

    const int M = MROWS;
    const size_t actN = (size_t)M * DM;

    split_act_kernel<<<(int)(actN / 256), 256>>>(x, x3, DM);
    split_wt_kernel<<<dim3(3 * DM / 32, DM / 32), dim3(32, 32)>>>(w_qkv, wq3, DM, 3 * DM);
    split_wt_kernel<<<dim3(DM / 32, DM / 32), dim3(32, 32)>>>(w_out, wo3, DM, DM);

    // QKV projection
    gemm_mma_kernel<<<dim3(3 * DM / 128, M / 128), 128, GEMM_SMEM>>>(
        x3, wq3, b_qkv, qkv, 3 * DM);

    // pre-split K and V
    kv_split_kernel<<<dim3(TS / 64, BB * NH), 256>>>(qkv, k2, vt);

    // attention
    attn_mma_kernel<<<dim3(TS / 64, BB * NH), 128, ATTN2_SMEM>>>(qkv, k2, vt, a3);

    // out projection
    gemm_mma_kernel<<<dim3(DM / 128, M / 128), 128, GEMM_SMEM>>>(
        a3, wo3, b_out, out, DM);
}